// round 17
// baseline (speedup 1.0000x reference)
#include <cuda_runtime.h>
#include <cuda_fp16.h>
#include <cstdint>

#define THREADS     512
#define FDIM        256
#define N_GEMM      24          // z1 = tanh(c), then 24 GEMM iterations (25 total)
#define FP8_LAST    13          // GEMM iters 1..13 run in fp8; 14..24 in fp16
#define N_PAIRS     1024        // 32768 rows / 32 rows per tile-pair

#define ROW_BYTES   512                          // fp16 z/W rows: 256 halfs
// ---- SMEM map ----
// [0,64K)    W8  : W*16 as e4m3, swizzled [n][k], 256B rows (persistent)
// [64K,192K) W16 : W as fp16, swizzled [n][k], 512B rows (persistent)
// [192K,224K) z region:
//    z16 A0 @ +0      z16 B0 @ +8K     z16 A1 @ +16K    z16 B1 @ +24K
//    z8  A0 @ +16K    z8  A1 @ +20K    z8  B0 @ +24K    z8  B1 @ +28K
//    (z8 lives where z16 buf1 sits; z8 is dead before z16 buf1 is first written)
#define W8_OFF      0
#define W16_OFF     65536
#define ZR_OFF      196608
#define SMEM_BYTES  229376                       // 224 KB
#define Z16A(p)     (ZR_OFF + (uint32_t)(p) * 16384u)
#define Z16B(p)     (ZR_OFF + 8192u + (uint32_t)(p) * 16384u)
#define Z8A(p)      (ZR_OFF + 16384u + (uint32_t)(p) * 4096u)
#define Z8B(p)      (ZR_OFF + 24576u + (uint32_t)(p) * 4096u)

static __device__ __forceinline__ uint32_t smem_u32(const void* p) {
    uint32_t a;
    asm("{ .reg .u64 t; cvta.to.shared.u64 t, %1; cvt.u32.u64 %0, t; }" : "=r"(a) : "l"(p));
    return a;
}

// fp16 tile swizzle (512B rows): 16B units XORed with (r&7)
static __device__ __forceinline__ uint32_t swz(uint32_t r, uint32_t k) {
    return r * ROW_BYTES + (((k >> 3) ^ (r & 7)) << 4) + ((k & 7) << 1);
}
// fp8 tile swizzle (256B rows, kb = byte column): 16 units/row, low-3 XOR
static __device__ __forceinline__ uint32_t swz8(uint32_t r, uint32_t kb) {
    uint32_t u = kb >> 4;
    u = (u & 8u) | ((u ^ r) & 7u);
    return r * 256u + (u << 4) + (kb & 15u);
}

static __device__ __forceinline__ void ldsm4(uint32_t r[4], uint32_t addr) {
    asm volatile("ldmatrix.sync.aligned.m8n8.x4.shared.b16 {%0,%1,%2,%3}, [%4];"
                 : "=r"(r[0]), "=r"(r[1]), "=r"(r[2]), "=r"(r[3]) : "r"(addr));
}

static __device__ __forceinline__ void mma16816(float d[4], const uint32_t a[4],
                                                uint32_t b0, uint32_t b1) {
    asm volatile("mma.sync.aligned.m16n8k16.row.col.f32.f16.f16.f32 "
                 "{%0,%1,%2,%3}, {%4,%5,%6,%7}, {%8,%9}, {%0,%1,%2,%3};"
                 : "+f"(d[0]), "+f"(d[1]), "+f"(d[2]), "+f"(d[3])
                 : "r"(a[0]), "r"(a[1]), "r"(a[2]), "r"(a[3]), "r"(b0), "r"(b1));
}

static __device__ __forceinline__ void mma_fp8(float d[4], const uint32_t a[4],
                                               uint32_t b0, uint32_t b1) {
    asm volatile("mma.sync.aligned.m16n8k32.row.col.f32.e4m3.e4m3.f32 "
                 "{%0,%1,%2,%3}, {%4,%5,%6,%7}, {%8,%9}, {%0,%1,%2,%3};"
                 : "+f"(d[0]), "+f"(d[1]), "+f"(d[2]), "+f"(d[3])
                 : "r"(a[0]), "r"(a[1]), "r"(a[2]), "r"(a[3]), "r"(b0), "r"(b1));
}

// Pack two f32 -> e4m3x2 (16 bits). First source -> UPPER byte (PTX cvt rule).
static __device__ __forceinline__ unsigned short fp8x2(float hi, float lo) {
    unsigned short r;
    asm("cvt.rn.satfinite.e4m3x2.f32 %0, %1, %2;" : "=h"(r) : "f"(hi), "f"(lo));
    return r;
}

static __device__ __forceinline__ uint32_t tanh_h2(uint32_t h2) {
    uint32_t y;
    asm("tanh.approx.f16x2 %0, %1;" : "=r"(y) : "r"(h2));
    return y;
}
static __device__ __forceinline__ float tanh_fast(float x) {
    float y;
    asm("tanh.approx.f32 %0, %1;" : "=f"(y) : "f"(x));
    return y;
}
// Accurate final-iteration tanh: 1 - 2/(1 + e^{2x}), ~1e-6 rel error.
static __device__ __forceinline__ float tanh_acc(float x) {
    float e, r;
    asm("ex2.approx.f32 %0, %1;" : "=f"(e) : "f"(x * 2.8853900817779268f));
    asm("rcp.approx.f32 %0, %1;" : "=f"(r) : "f"(1.0f + e));
    return 1.0f - 2.0f * r;
}

__global__ void __launch_bounds__(THREADS, 1)
fixed_point_kernel(const float* __restrict__ x, const float* __restrict__ W,
                   const float* __restrict__ b, float* __restrict__ out)
{
    extern __shared__ char smem[];
    const uint32_t sb = smem_u32(smem);

    const int tid = threadIdx.x;
    const int l   = tid & 31;
    const int wid = tid >> 5;
    const int wn  = wid << 4;                 // warp's 16-col slice of N=256
    const int qr  = l >> 2;
    const int qc  = (l & 3) << 1;

    // ---- One-time: W16 (fp16, 512B rows) and W8 (e4m3 of W*16, 256B rows) ----
    for (int idx = tid; idx < FDIM * (FDIM / 4); idx += THREADS) {
        int n  = idx >> 6;
        int k4 = (idx & 63) << 2;
        float4 wv = *reinterpret_cast<const float4*>(W + n * FDIM + k4);
        __half2 h0 = __floats2half2_rn(wv.x, wv.y);
        __half2 h1 = __floats2half2_rn(wv.z, wv.w);
        uint2 v16;
        v16.x = *reinterpret_cast<uint32_t*>(&h0);
        v16.y = *reinterpret_cast<uint32_t*>(&h1);
        *reinterpret_cast<uint2*>(smem + W16_OFF + swz(n, k4)) = v16;
        unsigned short p0 = fp8x2(wv.y * 16.0f, wv.x * 16.0f);
        unsigned short p1 = fp8x2(wv.w * 16.0f, wv.z * 16.0f);
        uint32_t v8 = (uint32_t)p0 | ((uint32_t)p1 << 16);
        *reinterpret_cast<uint32_t*>(smem + W8_OFF + swz8((uint32_t)n, (uint32_t)k4)) = v8;
    }
    __syncthreads();

    // Fragment addressing (shared row mapping with R14)
    const uint32_t a_r    = (uint32_t)(((l >> 3) & 1) * 8 + (l & 7));
    const uint32_t a_k16  = (uint32_t)(((l >> 4) & 1) * 8);           // fp16: elements
    const uint32_t a_k8   = (uint32_t)(((l >> 4) & 1) * 16);          // fp8: bytes
    const uint32_t b_r16  = (uint32_t)(wn + ((l >> 4) & 1) * 8 + (l & 7));
    const uint32_t b_k16  = (uint32_t)(((l >> 3) & 1) * 8);
    const uint32_t b_r8   = b_r16;
    const uint32_t b_k8   = (uint32_t)(((l >> 3) & 1) * 16);

    // ---- Persistent loop over 32-row tile pairs ----
    for (int pair = blockIdx.x; pair < N_PAIRS; pair += gridDim.x) {
        const int row0 = pair * 32;           // tile A rows [row0,row0+16), B next 16

        // c = x + b, packed half2
        uint32_t cA2[4], cB2[4];
#pragma unroll
        for (int h = 0; h < 2; ++h) {
            const float* xrA = x + (size_t)(row0 + qr + h * 8) * FDIM;
            const float* xrB = xrA + 16 * FDIM;
#pragma unroll
            for (int nf = 0; nf < 2; ++nf) {
                int c0 = wn + nf * 8 + qc;
                float2 bv = *reinterpret_cast<const float2*>(b + c0);
                float2 xa = *reinterpret_cast<const float2*>(xrA + c0);
                float2 xb = *reinterpret_cast<const float2*>(xrB + c0);
                __half2 ha = __floats2half2_rn(xa.x + bv.x, xa.y + bv.y);
                __half2 hb = __floats2half2_rn(xb.x + bv.x, xb.y + bv.y);
                cA2[nf * 2 + h] = *reinterpret_cast<uint32_t*>(&ha);
                cB2[nf * 2 + h] = *reinterpret_cast<uint32_t*>(&hb);
            }
        }

        // Iteration 0: z1 = tanh(c) -> z8 buf0 (e4m3)
#pragma unroll
        for (int nf = 0; nf < 2; ++nf) {
            int c0 = wn + nf * 8 + qc;
#pragma unroll
            for (int t = 0; t < 2; ++t) {     // t=0 tile A, t=1 tile B
                const uint32_t* c2 = t ? cB2 : cA2;
                uint32_t dst = t ? Z8B(0) : Z8A(0);
                float2 f0 = __half22float2(*reinterpret_cast<const __half2*>(&c2[nf * 2 + 0]));
                float2 f1 = __half22float2(*reinterpret_cast<const __half2*>(&c2[nf * 2 + 1]));
                unsigned short v0 = fp8x2(tanh_fast(f0.y), tanh_fast(f0.x));
                unsigned short v1 = fp8x2(tanh_fast(f1.y), tanh_fast(f1.x));
                *reinterpret_cast<unsigned short*>(smem + dst + swz8(qr,     (uint32_t)c0)) = v0;
                *reinterpret_cast<unsigned short*>(smem + dst + swz8(qr + 8, (uint32_t)c0)) = v1;
            }
        }
        __syncthreads();

        // ---- fp8 GEMM iterations 1..FP8_LAST ----
        float accA[2][4], accB[2][4];
#pragma unroll 1
        for (int it = 1; it <= FP8_LAST; ++it) {
            const uint32_t srcA8 = sb + Z8A((it - 1) & 1);
            const uint32_t srcB8 = sb + Z8B((it - 1) & 1);

#pragma unroll
            for (int nf = 0; nf < 2; ++nf)
#pragma unroll
                for (int j = 0; j < 4; ++j) { accA[nf][j] = 0.0f; accB[nf][j] = 0.0f; }

#pragma unroll
            for (int ks = 0; ks < 8; ++ks) {          // K = 256 as 8 steps of k32
                uint32_t aA[4], aB[4], bf[4];
                ldsm4(aA, srcA8 + swz8(a_r, (uint32_t)(ks * 32) + a_k8));
                ldsm4(aB, srcB8 + swz8(a_r, (uint32_t)(ks * 32) + a_k8));
                ldsm4(bf, sb + W8_OFF + swz8(b_r8, (uint32_t)(ks * 32) + b_k8));
                mma_fp8(accA[0], aA, bf[0], bf[1]);
                mma_fp8(accB[0], aB, bf[0], bf[1]);
                mma_fp8(accA[1], aA, bf[2], bf[3]);
                mma_fp8(accB[1], aB, bf[2], bf[3]);
            }

            // Epilogue: p = acc/16 + c ; tanh ; store fp8 (interior) or fp16 (it==FP8_LAST)
#pragma unroll
            for (int nf = 0; nf < 2; ++nf) {
                int c0 = wn + nf * 8 + qc;
#pragma unroll
                for (int t = 0; t < 2; ++t) {
                    const float (*ac)[4] = t ? accB : accA;
                    const uint32_t* c2 = t ? cB2 : cA2;
                    float2 f0 = __half22float2(*reinterpret_cast<const __half2*>(&c2[nf * 2 + 0]));
                    float2 f1 = __half22float2(*reinterpret_cast<const __half2*>(&c2[nf * 2 + 1]));
                    float t0 = tanh_fast(fmaf(ac[nf][0], 0.0625f, f0.x));
                    float t1 = tanh_fast(fmaf(ac[nf][1], 0.0625f, f0.y));
                    float t2 = tanh_fast(fmaf(ac[nf][2], 0.0625f, f1.x));
                    float t3 = tanh_fast(fmaf(ac[nf][3], 0.0625f, f1.y));
                    if (it < FP8_LAST) {
                        uint32_t dst = t ? Z8B(it & 1) : Z8A(it & 1);
                        *reinterpret_cast<unsigned short*>(smem + dst + swz8(qr,     (uint32_t)c0)) = fp8x2(t1, t0);
                        *reinterpret_cast<unsigned short*>(smem + dst + swz8(qr + 8, (uint32_t)c0)) = fp8x2(t3, t2);
                    } else {                           // transition: write z16 buf0
                        uint32_t dst = t ? Z16B(0) : Z16A(0);
                        __half2 h0 = __floats2half2_rn(t0, t1);
                        __half2 h1 = __floats2half2_rn(t2, t3);
                        *reinterpret_cast<uint32_t*>(smem + dst + swz(qr,     (uint32_t)c0)) =
                            *reinterpret_cast<uint32_t*>(&h0);
                        *reinterpret_cast<uint32_t*>(smem + dst + swz(qr + 8, (uint32_t)c0)) =
                            *reinterpret_cast<uint32_t*>(&h1);
                    }
                }
            }
            __syncthreads();
        }

        // ---- Per-pair Breg16 load (W16 smem is read-only resident) ----
        uint32_t Breg[64];
#pragma unroll
        for (int ks = 0; ks < 16; ++ks)
            ldsm4(&Breg[ks * 4], sb + W16_OFF + swz(b_r16, (uint32_t)(ks * 16) + b_k16));

        // ---- fp16 interleaved dual-tile iterations FP8_LAST+1 .. 23 (R14 core) ----
        uint32_t aA[2][4], aB[2][4];
#pragma unroll 1
        for (int it = FP8_LAST + 1; it < N_GEMM; ++it) {
            const uint32_t srcp = (uint32_t)((it - (FP8_LAST + 1)) & 1);
            const uint32_t dstp = srcp ^ 1u;
            const uint32_t ZAsrc = sb + Z16A(srcp);
            const uint32_t ZBsrc = sb + Z16B(srcp);
            const uint32_t zAdst = Z16A(dstp);
            const uint32_t zBdst = Z16B(dstp);

#pragma unroll
            for (int nf = 0; nf < 2; ++nf)
#pragma unroll
                for (int h = 0; h < 2; ++h) {
                    float2 fa = __half22float2(*reinterpret_cast<__half2*>(&cA2[nf * 2 + h]));
                    float2 fb = __half22float2(*reinterpret_cast<__half2*>(&cB2[nf * 2 + h]));
                    accA[nf][h * 2 + 0] = fa.x; accA[nf][h * 2 + 1] = fa.y;
                    accB[nf][h * 2 + 0] = fb.x; accB[nf][h * 2 + 1] = fb.y;
                }

            ldsm4(aA[0], ZAsrc + swz(a_r, a_k16));
            ldsm4(aB[0], ZBsrc + swz(a_r, a_k16));
#pragma unroll
            for (int ks = 0; ks < 16; ++ks) {
                const int cur = ks & 1, nxt = cur ^ 1;
                if (ks < 15) {
                    ldsm4(aA[nxt], ZAsrc + swz(a_r, (uint32_t)((ks + 1) * 16) + a_k16));
                    ldsm4(aB[nxt], ZBsrc + swz(a_r, (uint32_t)((ks + 1) * 16) + a_k16));
                }
                const uint32_t* Bk = &Breg[ks * 4];
                mma16816(accA[0], aA[cur], Bk[0], Bk[1]);
                mma16816(accB[0], aB[cur], Bk[0], Bk[1]);
                mma16816(accA[1], aA[cur], Bk[2], Bk[3]);
                mma16816(accB[1], aB[cur], Bk[2], Bk[3]);
            }

#pragma unroll
            for (int nf = 0; nf < 2; ++nf) {
                int c0 = wn + nf * 8 + qc;
                __half2 a0 = __floats2half2_rn(accA[nf][0], accA[nf][1]);
                __half2 a1 = __floats2half2_rn(accA[nf][2], accA[nf][3]);
                __half2 b0 = __floats2half2_rn(accB[nf][0], accB[nf][1]);
                __half2 b1 = __floats2half2_rn(accB[nf][2], accB[nf][3]);
                *reinterpret_cast<uint32_t*>(smem + zAdst + swz(qr,     (uint32_t)c0)) =
                    tanh_h2(*reinterpret_cast<uint32_t*>(&a0));
                *reinterpret_cast<uint32_t*>(smem + zAdst + swz(qr + 8, (uint32_t)c0)) =
                    tanh_h2(*reinterpret_cast<uint32_t*>(&a1));
                *reinterpret_cast<uint32_t*>(smem + zBdst + swz(qr,     (uint32_t)c0)) =
                    tanh_h2(*reinterpret_cast<uint32_t*>(&b0));
                *reinterpret_cast<uint32_t*>(smem + zBdst + swz(qr + 8, (uint32_t)c0)) =
                    tanh_h2(*reinterpret_cast<uint32_t*>(&b1));
            }
            __syncthreads();
        }

        // ---- Final iteration it=24 (src = z16 buf0): accurate tanh -> gmem ----
        {
            const uint32_t ZAsrc = sb + Z16A(0);
            const uint32_t ZBsrc = sb + Z16B(0);
#pragma unroll
            for (int nf = 0; nf < 2; ++nf)
#pragma unroll
                for (int h = 0; h < 2; ++h) {
                    float2 fa = __half22float2(*reinterpret_cast<__half2*>(&cA2[nf * 2 + h]));
                    float2 fb = __half22float2(*reinterpret_cast<__half2*>(&cB2[nf * 2 + h]));
                    accA[nf][h * 2 + 0] = fa.x; accA[nf][h * 2 + 1] = fa.y;
                    accB[nf][h * 2 + 0] = fb.x; accB[nf][h * 2 + 1] = fb.y;
                }
            ldsm4(aA[0], ZAsrc + swz(a_r, a_k16));
            ldsm4(aB[0], ZBsrc + swz(a_r, a_k16));
#pragma unroll
            for (int ks = 0; ks < 16; ++ks) {
                const int cur = ks & 1, nxt = cur ^ 1;
                if (ks < 15) {
                    ldsm4(aA[nxt], ZAsrc + swz(a_r, (uint32_t)((ks + 1) * 16) + a_k16));
                    ldsm4(aB[nxt], ZBsrc + swz(a_r, (uint32_t)((ks + 1) * 16) + a_k16));
                }
                const uint32_t* Bk = &Breg[ks * 4];
                mma16816(accA[0], aA[cur], Bk[0], Bk[1]);
                mma16816(accB[0], aB[cur], Bk[0], Bk[1]);
                mma16816(accA[1], aA[cur], Bk[2], Bk[3]);
                mma16816(accB[1], aB[cur], Bk[2], Bk[3]);
            }
#pragma unroll
            for (int nf = 0; nf < 2; ++nf) {
                int c0 = wn + nf * 8 + qc;
                int rgA = row0 + qr;
                int rgB = row0 + 16 + qr;
                float2 vA0 = make_float2(tanh_acc(accA[nf][0]), tanh_acc(accA[nf][1]));
                float2 vA1 = make_float2(tanh_acc(accA[nf][2]), tanh_acc(accA[nf][3]));
                float2 vB0 = make_float2(tanh_acc(accB[nf][0]), tanh_acc(accB[nf][1]));
                float2 vB1 = make_float2(tanh_acc(accB[nf][2]), tanh_acc(accB[nf][3]));
                *reinterpret_cast<float2*>(out + (size_t)rgA * FDIM + c0)       = vA0;
                *reinterpret_cast<float2*>(out + (size_t)(rgA + 8) * FDIM + c0) = vA1;
                *reinterpret_cast<float2*>(out + (size_t)rgB * FDIM + c0)       = vB0;
                *reinterpret_cast<float2*>(out + (size_t)(rgB + 8) * FDIM + c0) = vB1;
            }
        }
        __syncthreads();   // z regions safe for next pair's iteration 0
    }
}

extern "C" void kernel_launch(void* const* d_in, const int* in_sizes, int n_in,
                              void* d_out, int out_size)
{
    (void)in_sizes; (void)n_in; (void)out_size;
    const float* x = (const float*)d_in[0];
    const float* W = (const float*)d_in[1];
    const float* b = (const float*)d_in[2];
    float* out = (float*)d_out;

    int dev = 0, sms = 0;
    cudaGetDevice(&dev);
    cudaDeviceGetAttribute(&sms, cudaDevAttrMultiProcessorCount, dev);
    int grid = sms > 0 ? sms : 128;
    if (grid > N_PAIRS) grid = N_PAIRS;

    cudaFuncSetAttribute(fixed_point_kernel, cudaFuncAttributeMaxDynamicSharedMemorySize, SMEM_BYTES);
    fixed_point_kernel<<<grid, THREADS, SMEM_BYTES>>>(x, W, b, out);
}